// round 3
// baseline (speedup 1.0000x reference)
#include <cuda_runtime.h>
#include <math.h>

// Problem constants
#define SQ   2048   // sequence length
#define HID  2048   // hidden size
#define NH   16     // heads
#define HD   128    // head dim
#define HALF 64     // head dim / 2
#define GS   128    // quant group size

// ---------------- device scratch (static allocations, allowed) ----------------
__device__ float g_w[4][(size_t)HID * HID];        // quantized weights  (64 MB)
__device__ float g_proj[(size_t)SQ * HID];         // raw projection     (16 MB)
__device__ float g_q[NH][SQ * HD];                 // Q per head         (16 MB)
__device__ float g_k[NH][SQ * HD];                 // K per head         (16 MB)
__device__ float g_v[NH][SQ * HD];                 // V per head         (16 MB)
__device__ float g_scores[NH][(size_t)SQ * SQ];    // scores/probs       (256 MB)
__device__ float g_attn[(size_t)SQ * HID];         // attention output   (16 MB)
__device__ float g_cos[SQ * HALF];
__device__ float g_sin[SQ * HALF];

// ---------------- RoPE tables ----------------
__global__ void rope_tables_kernel() {
    int s = blockIdx.x, i = threadIdx.x;  // i in [0,64)
    float inv = (float)(1.0 / pow(10000.0, (double)i / 64.0));
    float ph = (float)s * inv;
    g_cos[s * HALF + i] = cosf(ph);
    g_sin[s * HALF + i] = sinf(ph);
}

// ---------------- ternary group-wise quantization ----------------
__device__ __forceinline__ float ternq(float w, float scale) {
    float wn = w / scale;
    float q = (wn > 0.5f) ? 1.0f : ((wn < -0.5f) ? -1.0f : 0.0f);
    return q * scale;
}

// one warp per 128-element group; groups are contiguous in row-major weights
__global__ void quantize_kernel(const float* __restrict__ w, float* __restrict__ o) {
    int gid  = blockIdx.x * 8 + (threadIdx.x >> 5);
    int lane = threadIdx.x & 31;
    size_t base = (size_t)gid * GS + lane * 4;
    float4 v = *reinterpret_cast<const float4*>(w + base);
    float s = fabsf(v.x) + fabsf(v.y) + fabsf(v.z) + fabsf(v.w);
#pragma unroll
    for (int off = 16; off; off >>= 1) s += __shfl_xor_sync(0xffffffffu, s, off);
    float scale = fmaxf(s * 0.0078125f, 1e-8f);  // mean = sum * (1/128), exact pow2
    float4 r;
    r.x = ternq(v.x, scale); r.y = ternq(v.y, scale);
    r.z = ternq(v.z, scale); r.w = ternq(v.w, scale);
    *reinterpret_cast<float4*>(o + base) = r;
}

// ---------------- tiled fp32 GEMM ----------------
// C[m,n] = alpha * sum_k A[m,k] * (BT ? B[n,k] : B[k,n])
// All dims assumed multiples of the tile sizes (true for this problem).
#define BM 128
#define BN 128
#define BKt 16
#define TM 8
#define TN 8
#define PAD 4

template<bool BT, bool CAUSAL, bool KCLIP>
__global__ __launch_bounds__(256)
void gemm_kernel(const float* __restrict__ A, const float* __restrict__ B,
                 float* __restrict__ C,
                 int K, int lda, int ldb, int ldc, float alpha,
                 long aStride, long bStride, long cStride)
{
    A += (size_t)blockIdx.z * aStride;
    B += (size_t)blockIdx.z * bStride;
    C += (size_t)blockIdx.z * cStride;
    int m0 = blockIdx.y * BM, n0 = blockIdx.x * BN;
    if (CAUSAL && n0 > m0) return;                 // fully above diagonal
    int kEnd = KCLIP ? min(K, m0 + BM) : K;        // causal K-clip for P@V

    __shared__ float As[BKt][BM + PAD];
    __shared__ float Bs[BKt][BN + PAD];
    int tid = threadIdx.x;
    int tr = tid >> 4, tc = tid & 15;

    float acc[TM][TN];
#pragma unroll
    for (int i = 0; i < TM; i++)
#pragma unroll
        for (int j = 0; j < TN; j++) acc[i][j] = 0.f;

    for (int k0 = 0; k0 < kEnd; k0 += BKt) {
#pragma unroll
        for (int i = 0; i < 2; i++) {
            int id  = tid + i * 256;      // 512 float4 per tile
            int row = id >> 2;            // 0..127
            int c4  = (id & 3) << 2;      // 0,4,8,12
            float4 va = *reinterpret_cast<const float4*>(A + (size_t)(m0 + row) * lda + k0 + c4);
            As[c4 + 0][row] = va.x; As[c4 + 1][row] = va.y;
            As[c4 + 2][row] = va.z; As[c4 + 3][row] = va.w;
            if (BT) {
                float4 vb = *reinterpret_cast<const float4*>(B + (size_t)(n0 + row) * ldb + k0 + c4);
                Bs[c4 + 0][row] = vb.x; Bs[c4 + 1][row] = vb.y;
                Bs[c4 + 2][row] = vb.z; Bs[c4 + 3][row] = vb.w;
            } else {
                int krow = id >> 5;           // 0..15
                int nc4  = (id & 31) << 2;    // 0..124
                float4 vb = *reinterpret_cast<const float4*>(B + (size_t)(k0 + krow) * ldb + n0 + nc4);
                *reinterpret_cast<float4*>(&Bs[krow][nc4]) = vb;
            }
        }
        __syncthreads();
#pragma unroll
        for (int kk = 0; kk < BKt; kk++) {
            float a[TM], b[TN];
            float4 t0 = *reinterpret_cast<const float4*>(&As[kk][tr * TM]);
            float4 t1 = *reinterpret_cast<const float4*>(&As[kk][tr * TM + 4]);
            a[0]=t0.x; a[1]=t0.y; a[2]=t0.z; a[3]=t0.w;
            a[4]=t1.x; a[5]=t1.y; a[6]=t1.z; a[7]=t1.w;
            float4 u0 = *reinterpret_cast<const float4*>(&Bs[kk][tc * TN]);
            float4 u1 = *reinterpret_cast<const float4*>(&Bs[kk][tc * TN + 4]);
            b[0]=u0.x; b[1]=u0.y; b[2]=u0.z; b[3]=u0.w;
            b[4]=u1.x; b[5]=u1.y; b[6]=u1.z; b[7]=u1.w;
#pragma unroll
            for (int i = 0; i < TM; i++)
#pragma unroll
                for (int j = 0; j < TN; j++) acc[i][j] += a[i] * b[j];
        }
        __syncthreads();
    }
#pragma unroll
    for (int i = 0; i < TM; i++) {
        float* cp = C + (size_t)(m0 + tr * TM + i) * ldc + n0 + tc * TN;
        float4 o0 = make_float4(acc[i][0]*alpha, acc[i][1]*alpha, acc[i][2]*alpha, acc[i][3]*alpha);
        float4 o1 = make_float4(acc[i][4]*alpha, acc[i][5]*alpha, acc[i][6]*alpha, acc[i][7]*alpha);
        *reinterpret_cast<float4*>(cp)     = o0;
        *reinterpret_cast<float4*>(cp + 4) = o1;
    }
}

// ---------------- RoPE + [s][h*128+d] -> [h][s][d] reshape ----------------
__global__ void rope_reshape_kernel(int which) {  // 0=q, 1=k, 2=v
    int s = blockIdx.x, h = blockIdx.y, d = threadIdx.x;  // d in [0,64)
    const float* src = g_proj + (size_t)s * HID + h * HD;
    if (which == 2) {
        float* dst = g_v[h] + (size_t)s * HD;
        dst[d] = src[d];
        dst[d + HALF] = src[d + HALF];
    } else {
        float* dst = (which == 0 ? g_q[h] : g_k[h]) + (size_t)s * HD;
        float x1 = src[d], x2 = src[d + HALF];
        float c = g_cos[s * HALF + d], sn = g_sin[s * HALF + d];
        dst[d] = x1 * c - x2 * sn;
        dst[d + HALF] = x1 * sn + x2 * c;
    }
}

// ---------------- causal softmax over scores rows ----------------
__global__ void softmax_kernel(const int* __restrict__ mask, float* __restrict__ scores) {
    int s = blockIdx.x;
    int h = blockIdx.y;
    float* row = scores + (size_t)h * SQ * SQ + (size_t)s * SQ;
    int tid = threadIdx.x;
    int n = s + 1;                       // valid keys (causal)
    __shared__ float red[256];

    float mx = -3.402823e38f;
    for (int t = tid; t < n; t += 256)
        if (mask[t]) mx = fmaxf(mx, row[t]);
    red[tid] = mx; __syncthreads();
    for (int off = 128; off; off >>= 1) {
        if (tid < off) red[tid] = fmaxf(red[tid], red[tid + off]);
        __syncthreads();
    }
    mx = red[0]; __syncthreads();

    float sum = 0.f;
    for (int t = tid; t < n; t += 256) {
        float e = mask[t] ? expf(row[t] - mx) : 0.f;
        row[t] = e;
        sum += e;
    }
    red[tid] = sum; __syncthreads();
    for (int off = 128; off; off >>= 1) {
        if (tid < off) red[tid] += red[tid + off];
        __syncthreads();
    }
    float inv = 1.f / red[0];
    for (int t = tid; t < n; t += 256) row[t] *= inv;
    for (int t = n + tid; t < SQ; t += 256) row[t] = 0.f;   // zero tail for P@V
}

// ---------------- launch ----------------
extern "C" void kernel_launch(void* const* d_in, const int* in_sizes, int n_in,
                              void* d_out, int out_size) {
    const float* x    = (const float*)d_in[0];
    const int*   mask = (const int*)d_in[1];
    const float* w_in[4] = {(const float*)d_in[2], (const float*)d_in[3],
                            (const float*)d_in[4], (const float*)d_in[5]};
    float* out = (float*)d_out;

    float *p_w, *p_proj, *p_q, *p_k, *p_v, *p_scores, *p_attn;
    cudaGetSymbolAddress((void**)&p_w,      g_w);
    cudaGetSymbolAddress((void**)&p_proj,   g_proj);
    cudaGetSymbolAddress((void**)&p_q,      g_q);
    cudaGetSymbolAddress((void**)&p_k,      g_k);
    cudaGetSymbolAddress((void**)&p_v,      g_v);
    cudaGetSymbolAddress((void**)&p_scores, g_scores);
    cudaGetSymbolAddress((void**)&p_attn,   g_attn);

    rope_tables_kernel<<<SQ, HALF>>>();

    // quantize all 4 weight matrices (32768 groups each, 8 warps/block)
    for (int m = 0; m < 4; m++)
        quantize_kernel<<<(HID * HID / GS) / 8, 256>>>(w_in[m], p_w + (size_t)m * HID * HID);

    // q/k/v projections (NT GEMM 2048^3) + fused-off rope/reshape
    for (int m = 0; m < 3; m++) {
        gemm_kernel<true, false, false><<<dim3(16, 16, 1), 256>>>(
            x, p_w + (size_t)m * HID * HID, p_proj,
            HID, HID, HID, HID, 1.0f, 0, 0, 0);
        rope_reshape_kernel<<<dim3(SQ, NH), HALF>>>(m);
    }

    // scores = (Q K^T) / sqrt(128), causal block skip, batched over heads
    const float s_alpha = 0.08838834764831845f;  // 1/sqrt(128)
    gemm_kernel<true, true, false><<<dim3(16, 16, NH), 256>>>(
        p_q, p_k, p_scores,
        HD, HD, HD, SQ, s_alpha,
        (long)SQ * HD, (long)SQ * HD, (long)SQ * SQ);

    softmax_kernel<<<dim3(SQ, NH), 256>>>(mask, p_scores);

    // attn = P @ V (NN GEMM, causal K-clip), written straight into [s][h*128+d]
    gemm_kernel<false, false, true><<<dim3(1, 16, NH), 256>>>(
        p_scores, p_v, p_attn,
        SQ, SQ, HD, HID, 1.0f,
        (long)SQ * SQ, (long)SQ * HD, (long)HD);

    // output projection (NT GEMM 2048^3) -> d_out
    gemm_kernel<true, false, false><<<dim3(16, 16, 1), 256>>>(
        p_attn, p_w + 3 * (size_t)HID * HID, out,
        HID, HID, HID, HID, 1.0f, 0, 0, 0);
}

// round 7
// speedup vs baseline: 2.3443x; 2.3443x over previous
#include <cuda_runtime.h>
#include <cuda_bf16.h>
#include <math.h>
#include <stdint.h>

#define SQ   2048
#define HID  2048
#define NH   16
#define HD   128
#define HALF 64
#define GS   128

// ======================= PTX helpers (baseline sm_103 — NO tcgen05) =======================
__device__ __forceinline__ uint32_t smem_u32(const void* p) {
    uint32_t a;
    asm("{ .reg .u64 t; cvta.to.shared.u64 t, %1; cvt.u32.u64 %0, t; }" : "=r"(a) : "l"(p));
    return a;
}
#define SW128(o) ((o) ^ (((o) >> 3) & 0x70))

#define CPASYNC16(dst, src) \
    asm volatile("cp.async.cg.shared.global [%0], [%1], 16;" :: "r"(dst), "l"(src))
#define CPCOMMIT() asm volatile("cp.async.commit_group;" ::: "memory")
#define CPWAIT1()  asm volatile("cp.async.wait_group 1;" ::: "memory")
#define CPWAIT0()  asm volatile("cp.async.wait_group 0;" ::: "memory")

#define LDSM4(r0, r1, r2, r3, addr) \
    asm volatile("ldmatrix.sync.aligned.m8n8.x4.shared.b16 {%0,%1,%2,%3}, [%4];" \
                 : "=r"(r0), "=r"(r1), "=r"(r2), "=r"(r3) : "r"(addr))
#define LDSM2(r0, r1, addr) \
    asm volatile("ldmatrix.sync.aligned.m8n8.x2.shared.b16 {%0,%1}, [%2];" \
                 : "=r"(r0), "=r"(r1) : "r"(addr))

#define MMA16816(d, a, b) \
    asm volatile("mma.sync.aligned.m16n8k16.row.col.f32.bf16.bf16.f32 " \
                 "{%0,%1,%2,%3}, {%4,%5,%6,%7}, {%8,%9}, {%0,%1,%2,%3};" \
                 : "+f"((d)[0]), "+f"((d)[1]), "+f"((d)[2]), "+f"((d)[3]) \
                 : "r"((a)[0]), "r"((a)[1]), "r"((a)[2]), "r"((a)[3]), \
                   "r"((b)[0]), "r"((b)[1]))

// ======================= device scratch =======================
__device__ __nv_bfloat16 g_wh[4][(size_t)HID * HID];
__device__ __nv_bfloat16 g_wl[4][(size_t)HID * HID];
__device__ __nv_bfloat16 g_xh[(size_t)SQ * HID];
__device__ __nv_bfloat16 g_xl[(size_t)SQ * HID];
__device__ float         g_proj[3][(size_t)SQ * HID];
__device__ __nv_bfloat16 g_qh[NH][SQ * HD], g_ql[NH][SQ * HD];
__device__ __nv_bfloat16 g_kh[NH][SQ * HD], g_kl[NH][SQ * HD];
__device__ __nv_bfloat16 g_vth[NH][HD * SQ], g_vtl[NH][HD * SQ];  // V^T [d][s]
__device__ float         g_scores[NH][(size_t)SQ * SQ];
__device__ __nv_bfloat16 g_ph[NH][(size_t)SQ * SQ], g_pl[NH][(size_t)SQ * SQ];
__device__ float         g_attn[(size_t)SQ * HID];
__device__ __nv_bfloat16 g_ah[(size_t)SQ * HID], g_al[(size_t)SQ * HID];
__device__ float         g_cos[SQ * HALF], g_sin[SQ * HALF];

__device__ __forceinline__ void bsplit(float x, __nv_bfloat16& h, __nv_bfloat16& l) {
    h = __float2bfloat16(x);
    l = __float2bfloat16(x - __bfloat162float(h));
}

// ======================= small kernels =======================
__global__ void rope_tables_kernel() {
    int s = blockIdx.x, i = threadIdx.x;
    float inv = (float)(1.0 / pow(10000.0, (double)i / 64.0));
    float ph = (float)s * inv;
    g_cos[s * HALF + i] = cosf(ph);
    g_sin[s * HALF + i] = sinf(ph);
}

__global__ void quantize_split_kernel(const float* __restrict__ w,
                                      __nv_bfloat16* __restrict__ oh,
                                      __nv_bfloat16* __restrict__ ol) {
    int gid  = blockIdx.x * 8 + (threadIdx.x >> 5);
    int lane = threadIdx.x & 31;
    size_t base = (size_t)gid * GS + lane * 4;
    float4 v = *reinterpret_cast<const float4*>(w + base);
    float s = fabsf(v.x) + fabsf(v.y) + fabsf(v.z) + fabsf(v.w);
#pragma unroll
    for (int off = 16; off; off >>= 1) s += __shfl_xor_sync(0xffffffffu, s, off);
    float scale = fmaxf(s * 0.0078125f, 1e-8f);
    float vv[4] = {v.x, v.y, v.z, v.w};
#pragma unroll
    for (int j = 0; j < 4; j++) {
        float wn = vv[j] / scale;
        float q  = (wn > 0.5f) ? 1.0f : ((wn < -0.5f) ? -1.0f : 0.0f);
        float wq = q * scale;
        __nv_bfloat16 hh, ll; bsplit(wq, hh, ll);
        oh[base + j] = hh; ol[base + j] = ll;
    }
}

__global__ void split_kernel(const float* __restrict__ x,
                             __nv_bfloat16* __restrict__ oh,
                             __nv_bfloat16* __restrict__ ol) {
    size_t i = ((size_t)blockIdx.x * 256 + threadIdx.x) * 4;
    float4 v = *reinterpret_cast<const float4*>(x + i);
    float vv[4] = {v.x, v.y, v.z, v.w};
    __nv_bfloat16 h[4], l[4];
#pragma unroll
    for (int j = 0; j < 4; j++) bsplit(vv[j], h[j], l[j]);
    reinterpret_cast<__nv_bfloat162*>(oh + i)[0] = {h[0], h[1]};
    reinterpret_cast<__nv_bfloat162*>(oh + i)[1] = {h[2], h[3]};
    reinterpret_cast<__nv_bfloat162*>(ol + i)[0] = {l[0], l[1]};
    reinterpret_cast<__nv_bfloat162*>(ol + i)[1] = {l[2], l[3]};
}

__global__ void rope_reshape_kernel(int which) {
    int s = blockIdx.x, h = blockIdx.y, d = threadIdx.x;  // d in [0,64)
    const float* src = g_proj[which] + (size_t)s * HID + h * HD;
    float x1 = src[d], x2 = src[d + HALF];
    float c = g_cos[s * HALF + d], sn = g_sin[s * HALF + d];
    float o1 = x1 * c - x2 * sn;
    float o2 = x1 * sn + x2 * c;
    __nv_bfloat16 h1, l1, h2, l2;
    bsplit(o1, h1, l1); bsplit(o2, h2, l2);
    __nv_bfloat16* dh = (which == 0 ? g_qh[h] : g_kh[h]) + (size_t)s * HD;
    __nv_bfloat16* dl = (which == 0 ? g_ql[h] : g_kl[h]) + (size_t)s * HD;
    dh[d] = h1; dh[d + HALF] = h2;
    dl[d] = l1; dl[d + HALF] = l2;
}

__global__ void vt_split_kernel() {
    __shared__ float t[32][33];
    int h = blockIdx.z, s0 = blockIdx.x * 32, d0 = blockIdx.y * 32;
    const float* src = g_proj[2] + (size_t)h * HD;
    for (int i = threadIdx.y; i < 32; i += 8)
        t[i][threadIdx.x] = src[(size_t)(s0 + i) * HID + d0 + threadIdx.x];
    __syncthreads();
    for (int i = threadIdx.y; i < 32; i += 8) {
        float v = t[threadIdx.x][i];
        __nv_bfloat16 hh, ll; bsplit(v, hh, ll);
        size_t off = (size_t)(d0 + i) * SQ + s0 + threadIdx.x;
        g_vth[h][off] = hh; g_vtl[h][off] = ll;
    }
}

__global__ void softmax_kernel(const int* __restrict__ mask) {
    int s = blockIdx.x, h = blockIdx.y, tid = threadIdx.x;
    const float* row = g_scores[h] + (size_t)s * SQ;
    __nv_bfloat16* ph = g_ph[h] + (size_t)s * SQ;
    __nv_bfloat16* pl = g_pl[h] + (size_t)s * SQ;
    __shared__ float red[8];

    float v[8]; bool ok[8];
#pragma unroll
    for (int j = 0; j < 8; j++) {
        int t = tid + j * 256;
        ok[j] = (t <= s) && (mask[t] != 0);
        float r = row[t];
        v[j] = ok[j] ? r : -3.402823e38f;
    }
    float mx = v[0];
#pragma unroll
    for (int j = 1; j < 8; j++) mx = fmaxf(mx, v[j]);
#pragma unroll
    for (int off = 16; off; off >>= 1) mx = fmaxf(mx, __shfl_xor_sync(0xffffffffu, mx, off));
    if ((tid & 31) == 0) red[tid >> 5] = mx;
    __syncthreads();
    mx = red[0];
#pragma unroll
    for (int j = 1; j < 8; j++) mx = fmaxf(mx, red[j]);
    __syncthreads();

    float e[8], sum = 0.f;
#pragma unroll
    for (int j = 0; j < 8; j++) {
        e[j] = ok[j] ? expf(v[j] - mx) : 0.f;
        sum += e[j];
    }
#pragma unroll
    for (int off = 16; off; off >>= 1) sum += __shfl_xor_sync(0xffffffffu, sum, off);
    if ((tid & 31) == 0) red[tid >> 5] = sum;
    __syncthreads();
    sum = 0.f;
#pragma unroll
    for (int j = 0; j < 8; j++) sum += red[j];
    float inv = 1.f / sum;
#pragma unroll
    for (int j = 0; j < 8; j++) {
        int t = tid + j * 256;
        __nv_bfloat16 hh, ll; bsplit(e[j] * inv, hh, ll);
        ph[t] = hh; pl[t] = ll;
    }
}

// ======================= HMMA split GEMM =======================
// C[m,n] = alpha * sum_k (Ah+Al)[m,k] * (Bh+Bl)[n,k]   (lo*lo dropped)
// A,B pieces K-major bf16. CTA tile 128x128, BK=32, double-buffered cp.async.
// SMEM stage: A 128 rows x 128B [hi|lo] swizzled, then B likewise. 32KB/stage.
#define STAGE_BYTES 32768
#define GEMM_SMEM   65536

template<bool CAUSAL, bool KCLIP>
__global__ void __launch_bounds__(256, 1)
gemm_mma(const __nv_bfloat16* __restrict__ Ah, const __nv_bfloat16* __restrict__ Al,
         const __nv_bfloat16* __restrict__ Bh, const __nv_bfloat16* __restrict__ Bl,
         float* __restrict__ C,
         int lda, int ldb, int ldc, int K, float alpha,
         long long aStr, long long bStr, long long cStr)
{
    int m0 = blockIdx.y * 128, n0 = blockIdx.x * 128;
    if (CAUSAL && n0 > m0) return;
    size_t z = blockIdx.z;
    Ah += z * aStr; Al += z * aStr;
    Bh += z * bStr; Bl += z * bStr;
    C  += z * cStr;
    int kEnd = KCLIP ? min(K, m0 + 128) : K;
    int S = kEnd >> 5;

    extern __shared__ char smem[];
    uint32_t sb = smem_u32(smem);
    int tid = threadIdx.x, lane = tid & 31, wid = tid >> 5;
    int wm = wid >> 2, wn = wid & 3;          // warp tile: rows wm*64, cols wn*32

    const __nv_bfloat16* Ahm = Ah + (size_t)m0 * lda;
    const __nv_bfloat16* Alm = Al + (size_t)m0 * lda;
    const __nv_bfloat16* Bhn = Bh + (size_t)n0 * ldb;
    const __nv_bfloat16* Bln = Bl + (size_t)n0 * ldb;

    float acc[4][4][4];
#pragma unroll
    for (int i = 0; i < 4; i++)
#pragma unroll
        for (int j = 0; j < 4; j++)
#pragma unroll
            for (int r = 0; r < 4; r++) acc[i][j][r] = 0.f;

    auto prefetch = [&](int s) {
        int k0 = s * 32;
        uint32_t buf = sb + (uint32_t)(s & 1) * STAGE_BYTES;
#pragma unroll
        for (int j = 0; j < 4; j++) {          // A: 1024 16B chunks
            int id = tid + j * 256;
            int row = id >> 3, ch = id & 7;    // ch<4: hi, ch>=4: lo
            const __nv_bfloat16* src =
                (ch < 4 ? Ahm : Alm) + (size_t)row * lda + k0 + (ch & 3) * 8;
            CPASYNC16(buf + SW128((uint32_t)(row * 128 + ch * 16)), src);
        }
#pragma unroll
        for (int j = 0; j < 4; j++) {          // B
            int id = tid + j * 256;
            int row = id >> 3, ch = id & 7;
            const __nv_bfloat16* src =
                (ch < 4 ? Bhn : Bln) + (size_t)row * ldb + k0 + (ch & 3) * 8;
            CPASYNC16(buf + 16384u + SW128((uint32_t)(row * 128 + ch * 16)), src);
        }
    };

    auto compute = [&](int s) {
        uint32_t bufA = sb + (uint32_t)(s & 1) * STAGE_BYTES;
        uint32_t bufB = bufA + 16384u;
        int la = lane & 15;
#pragma unroll
        for (int kk = 0; kk < 2; kk++) {
            uint32_t ah[4][4], al[4][4], bh[4][2], bl[4][2];
#pragma unroll
            for (int i = 0; i < 4; i++) {
                uint32_t row = (uint32_t)(wm * 64 + i * 16 + (lane & 15));
                uint32_t colh = (uint32_t)(kk * 32 + (lane >> 4) * 16);
                LDSM4(ah[i][0], ah[i][1], ah[i][2], ah[i][3],
                      bufA + SW128(row * 128 + colh));
                LDSM4(al[i][0], al[i][1], al[i][2], al[i][3],
                      bufA + SW128(row * 128 + 64 + colh));
            }
#pragma unroll
            for (int j = 0; j < 4; j++) {
                uint32_t row = (uint32_t)(wn * 32 + j * 8 + (la & 7));
                uint32_t colh = (uint32_t)(kk * 32 + (la >> 3) * 16);
                LDSM2(bh[j][0], bh[j][1], bufB + SW128(row * 128 + colh));
                LDSM2(bl[j][0], bl[j][1], bufB + SW128(row * 128 + 64 + colh));
            }
#pragma unroll
            for (int i = 0; i < 4; i++)
#pragma unroll
                for (int j = 0; j < 4; j++) {
                    MMA16816(acc[i][j], ah[i], bh[j]);
                    MMA16816(acc[i][j], ah[i], bl[j]);
                    MMA16816(acc[i][j], al[i], bh[j]);
                }
        }
    };

    prefetch(0); CPCOMMIT();
    for (int s = 0; s < S; s++) {
        if (s + 1 < S) { prefetch(s + 1); CPCOMMIT(); CPWAIT1(); }
        else           { CPWAIT0(); }
        __syncthreads();
        compute(s);
        __syncthreads();
    }

    // epilogue
    int r0 = m0 + wm * 64, c0 = n0 + wn * 32;
#pragma unroll
    for (int i = 0; i < 4; i++)
#pragma unroll
        for (int j = 0; j < 4; j++) {
            int row = r0 + i * 16 + (lane >> 2);
            int col = c0 + j * 8 + (lane & 3) * 2;
            float2 o0 = make_float2(acc[i][j][0] * alpha, acc[i][j][1] * alpha);
            float2 o1 = make_float2(acc[i][j][2] * alpha, acc[i][j][3] * alpha);
            *reinterpret_cast<float2*>(C + (size_t)row * ldc + col) = o0;
            *reinterpret_cast<float2*>(C + (size_t)(row + 8) * ldc + col) = o1;
        }
}

// ======================= launch =======================
extern "C" void kernel_launch(void* const* d_in, const int* in_sizes, int n_in,
                              void* d_out, int out_size) {
    const float* x    = (const float*)d_in[0];
    const int*   mask = (const int*)d_in[1];
    const float* w_in[4] = {(const float*)d_in[2], (const float*)d_in[3],
                            (const float*)d_in[4], (const float*)d_in[5]};
    float* out = (float*)d_out;

    __nv_bfloat16 *p_wh, *p_wl, *p_xh, *p_xl, *p_qh, *p_ql, *p_kh, *p_kl;
    __nv_bfloat16 *p_vth, *p_vtl, *p_ph, *p_pl, *p_ah, *p_al;
    float *p_proj, *p_scores, *p_attn;
    cudaGetSymbolAddress((void**)&p_wh,     g_wh);
    cudaGetSymbolAddress((void**)&p_wl,     g_wl);
    cudaGetSymbolAddress((void**)&p_xh,     g_xh);
    cudaGetSymbolAddress((void**)&p_xl,     g_xl);
    cudaGetSymbolAddress((void**)&p_proj,   g_proj);
    cudaGetSymbolAddress((void**)&p_qh,     g_qh);
    cudaGetSymbolAddress((void**)&p_ql,     g_ql);
    cudaGetSymbolAddress((void**)&p_kh,     g_kh);
    cudaGetSymbolAddress((void**)&p_kl,     g_kl);
    cudaGetSymbolAddress((void**)&p_vth,    g_vth);
    cudaGetSymbolAddress((void**)&p_vtl,    g_vtl);
    cudaGetSymbolAddress((void**)&p_scores, g_scores);
    cudaGetSymbolAddress((void**)&p_ph,     g_ph);
    cudaGetSymbolAddress((void**)&p_pl,     g_pl);
    cudaGetSymbolAddress((void**)&p_attn,   g_attn);
    cudaGetSymbolAddress((void**)&p_ah,     g_ah);
    cudaGetSymbolAddress((void**)&p_al,     g_al);

    cudaFuncSetAttribute(gemm_mma<false, false>,
        cudaFuncAttributeMaxDynamicSharedMemorySize, GEMM_SMEM);
    cudaFuncSetAttribute(gemm_mma<true, false>,
        cudaFuncAttributeMaxDynamicSharedMemorySize, GEMM_SMEM);
    cudaFuncSetAttribute(gemm_mma<false, true>,
        cudaFuncAttributeMaxDynamicSharedMemorySize, GEMM_SMEM);

    rope_tables_kernel<<<SQ, HALF>>>();

    for (int m = 0; m < 4; m++)
        quantize_split_kernel<<<(HID * HID / GS) / 8, 256>>>(
            w_in[m], p_wh + (size_t)m * HID * HID, p_wl + (size_t)m * HID * HID);

    split_kernel<<<(SQ * HID) / 1024, 256>>>(x, p_xh, p_xl);

    // q,k,v projections batched over z
    gemm_mma<false, false><<<dim3(16, 16, 3), 256, GEMM_SMEM>>>(
        p_xh, p_xl, p_wh, p_wl, p_proj,
        HID, HID, HID, HID, 1.0f,
        0LL, (long long)HID * HID, (long long)SQ * HID);

    rope_reshape_kernel<<<dim3(SQ, NH), HALF>>>(0);
    rope_reshape_kernel<<<dim3(SQ, NH), HALF>>>(1);
    vt_split_kernel<<<dim3(SQ / 32, HD / 32, NH), dim3(32, 8)>>>();

    // scores = (Q K^T)/sqrt(128), causal tile skip, batched over heads
    gemm_mma<true, false><<<dim3(16, 16, NH), 256, GEMM_SMEM>>>(
        p_qh, p_ql, p_kh, p_kl, p_scores,
        HD, HD, SQ, HD, 0.08838834764831845f,
        (long long)SQ * HD, (long long)SQ * HD, (long long)SQ * SQ);

    softmax_kernel<<<dim3(SQ, NH), 256>>>(mask);

    // attn = P @ V (B = V transposed to K-major), causal K-clip
    gemm_mma<false, true><<<dim3(1, 16, NH), 256, GEMM_SMEM>>>(
        p_ph, p_pl, p_vth, p_vtl, p_attn,
        SQ, SQ, HID, SQ, 1.0f,
        (long long)SQ * SQ, (long long)HD * SQ, (long long)HD);

    split_kernel<<<(SQ * HID) / 1024, 256>>>(p_attn, p_ah, p_al);

    // output projection
    gemm_mma<false, false><<<dim3(16, 16, 1), 256, GEMM_SMEM>>>(
        p_ah, p_al, p_wh + 3 * (size_t)HID * HID, p_wl + 3 * (size_t)HID * HID, out,
        HID, HID, HID, HID, 1.0f, 0LL, 0LL, 0LL);
}

// round 8
// speedup vs baseline: 2.8253x; 1.2052x over previous
#include <cuda_runtime.h>
#include <cuda_bf16.h>
#include <math.h>
#include <stdint.h>

#define SQ   2048
#define HID  2048
#define NH   16
#define HD   128
#define HALF 64
#define GS   128

// ======================= PTX helpers (baseline sm_103 — NO tcgen05) =======================
__device__ __forceinline__ uint32_t smem_u32(const void* p) {
    uint32_t a;
    asm("{ .reg .u64 t; cvta.to.shared.u64 t, %1; cvt.u32.u64 %0, t; }" : "=r"(a) : "l"(p));
    return a;
}
#define SW128(o) ((o) ^ (((o) >> 3) & 0x70))
#define SW64(o)  ((o) ^ (((o) >> 3) & 0x30))

#define CPASYNC16(dst, src) \
    asm volatile("cp.async.cg.shared.global [%0], [%1], 16;" :: "r"(dst), "l"(src))
#define CPCOMMIT() asm volatile("cp.async.commit_group;" ::: "memory")
#define CPWAIT1()  asm volatile("cp.async.wait_group 1;" ::: "memory")
#define CPWAIT0()  asm volatile("cp.async.wait_group 0;" ::: "memory")

#define LDSM4(r0, r1, r2, r3, addr) \
    asm volatile("ldmatrix.sync.aligned.m8n8.x4.shared.b16 {%0,%1,%2,%3}, [%4];" \
                 : "=r"(r0), "=r"(r1), "=r"(r2), "=r"(r3) : "r"(addr))
#define LDSM2(r0, r1, addr) \
    asm volatile("ldmatrix.sync.aligned.m8n8.x2.shared.b16 {%0,%1}, [%2];" \
                 : "=r"(r0), "=r"(r1) : "r"(addr))

#define MMA16816(d, a, b) \
    asm volatile("mma.sync.aligned.m16n8k16.row.col.f32.bf16.bf16.f32 " \
                 "{%0,%1,%2,%3}, {%4,%5,%6,%7}, {%8,%9}, {%0,%1,%2,%3};" \
                 : "+f"((d)[0]), "+f"((d)[1]), "+f"((d)[2]), "+f"((d)[3]) \
                 : "r"((a)[0]), "r"((a)[1]), "r"((a)[2]), "r"((a)[3]), \
                   "r"((b)[0]), "r"((b)[1]))

// ======================= device scratch =======================
__device__ __nv_bfloat16 g_wq[4][(size_t)HID * HID];     // ternary q in bf16 (exact)
__device__ float         g_wsc[4][(size_t)HID * 16];     // per-row per-K-group scales
__device__ __nv_bfloat16 g_xh[(size_t)SQ * HID];
__device__ __nv_bfloat16 g_xl[(size_t)SQ * HID];
__device__ float         g_proj[3][(size_t)SQ * HID];
__device__ __nv_bfloat16 g_qh[NH][SQ * HD], g_ql[NH][SQ * HD];
__device__ __nv_bfloat16 g_kh[NH][SQ * HD], g_kl[NH][SQ * HD];
__device__ __nv_bfloat16 g_vth[NH][HD * SQ], g_vtl[NH][HD * SQ];  // V^T [d][s]
__device__ float         g_scores[NH][(size_t)SQ * SQ];
__device__ __nv_bfloat16 g_ph[NH][(size_t)SQ * SQ], g_pl[NH][(size_t)SQ * SQ];
__device__ float         g_attn[(size_t)SQ * HID];
__device__ __nv_bfloat16 g_ah[(size_t)SQ * HID], g_al[(size_t)SQ * HID];
__device__ float         g_cos[SQ * HALF], g_sin[SQ * HALF];

__device__ __forceinline__ void bsplit(float x, __nv_bfloat16& h, __nv_bfloat16& l) {
    h = __float2bfloat16(x);
    l = __float2bfloat16(x - __bfloat162float(h));
}

// ======================= small kernels =======================
__global__ void rope_tables_kernel() {
    int s = blockIdx.x, i = threadIdx.x;
    float inv = (float)(1.0 / pow(10000.0, (double)i / 64.0));
    float ph = (float)s * inv;
    g_cos[s * HALF + i] = cosf(ph);
    g_sin[s * HALF + i] = sinf(ph);
}

// one warp per 128-elem group; emit exact ternary bf16 q + fp32 group scale
__global__ void quantize_tern_kernel(const float* __restrict__ w,
                                     __nv_bfloat16* __restrict__ q,
                                     float* __restrict__ sc) {
    int gid  = blockIdx.x * 8 + (threadIdx.x >> 5);   // = n*16 + g
    int lane = threadIdx.x & 31;
    size_t base = (size_t)gid * GS + lane * 4;
    float4 v = *reinterpret_cast<const float4*>(w + base);
    float s = fabsf(v.x) + fabsf(v.y) + fabsf(v.z) + fabsf(v.w);
#pragma unroll
    for (int off = 16; off; off >>= 1) s += __shfl_xor_sync(0xffffffffu, s, off);
    float scale = fmaxf(s * 0.0078125f, 1e-8f);
    float vv[4] = {v.x, v.y, v.z, v.w};
    __nv_bfloat16 qv[4];
#pragma unroll
    for (int j = 0; j < 4; j++) {
        float wn = vv[j] / scale;
        qv[j] = __float2bfloat16((wn > 0.5f) ? 1.0f : ((wn < -0.5f) ? -1.0f : 0.0f));
    }
    reinterpret_cast<__nv_bfloat162*>(q + base)[0] = {qv[0], qv[1]};
    reinterpret_cast<__nv_bfloat162*>(q + base)[1] = {qv[2], qv[3]};
    if (lane == 0) sc[gid] = scale;   // sc layout: [n][16]
}

__global__ void split_kernel(const float* __restrict__ x,
                             __nv_bfloat16* __restrict__ oh,
                             __nv_bfloat16* __restrict__ ol) {
    size_t i = ((size_t)blockIdx.x * 256 + threadIdx.x) * 4;
    float4 v = *reinterpret_cast<const float4*>(x + i);
    float vv[4] = {v.x, v.y, v.z, v.w};
    __nv_bfloat16 h[4], l[4];
#pragma unroll
    for (int j = 0; j < 4; j++) bsplit(vv[j], h[j], l[j]);
    reinterpret_cast<__nv_bfloat162*>(oh + i)[0] = {h[0], h[1]};
    reinterpret_cast<__nv_bfloat162*>(oh + i)[1] = {h[2], h[3]};
    reinterpret_cast<__nv_bfloat162*>(ol + i)[0] = {l[0], l[1]};
    reinterpret_cast<__nv_bfloat162*>(ol + i)[1] = {l[2], l[3]};
}

__global__ void rope_reshape_kernel(int which) {
    int s = blockIdx.x, h = blockIdx.y, d = threadIdx.x;  // d in [0,64)
    const float* src = g_proj[which] + (size_t)s * HID + h * HD;
    float x1 = src[d], x2 = src[d + HALF];
    float c = g_cos[s * HALF + d], sn = g_sin[s * HALF + d];
    float o1 = x1 * c - x2 * sn;
    float o2 = x1 * sn + x2 * c;
    __nv_bfloat16 h1, l1, h2, l2;
    bsplit(o1, h1, l1); bsplit(o2, h2, l2);
    __nv_bfloat16* dh = (which == 0 ? g_qh[h] : g_kh[h]) + (size_t)s * HD;
    __nv_bfloat16* dl = (which == 0 ? g_ql[h] : g_kl[h]) + (size_t)s * HD;
    dh[d] = h1; dh[d + HALF] = h2;
    dl[d] = l1; dl[d + HALF] = l2;
}

__global__ void vt_split_kernel() {
    __shared__ float t[32][33];
    int h = blockIdx.z, s0 = blockIdx.x * 32, d0 = blockIdx.y * 32;
    const float* src = g_proj[2] + (size_t)h * HD;
    for (int i = threadIdx.y; i < 32; i += 8)
        t[i][threadIdx.x] = src[(size_t)(s0 + i) * HID + d0 + threadIdx.x];
    __syncthreads();
    for (int i = threadIdx.y; i < 32; i += 8) {
        float v = t[threadIdx.x][i];
        __nv_bfloat16 hh, ll; bsplit(v, hh, ll);
        size_t off = (size_t)(d0 + i) * SQ + s0 + threadIdx.x;
        g_vth[h][off] = hh; g_vtl[h][off] = ll;
    }
}

__global__ void softmax_kernel(const int* __restrict__ mask) {
    int s = blockIdx.x, h = blockIdx.y, tid = threadIdx.x;
    const float* row = g_scores[h] + (size_t)s * SQ;
    __nv_bfloat16* ph = g_ph[h] + (size_t)s * SQ;
    __nv_bfloat16* pl = g_pl[h] + (size_t)s * SQ;
    __shared__ float red[8];

    float v[8]; bool ok[8];
#pragma unroll
    for (int j = 0; j < 8; j++) {
        int t = tid + j * 256;
        ok[j] = (t <= s) && (mask[t] != 0);
        float r = row[t];
        v[j] = ok[j] ? r : -3.402823e38f;
    }
    float mx = v[0];
#pragma unroll
    for (int j = 1; j < 8; j++) mx = fmaxf(mx, v[j]);
#pragma unroll
    for (int off = 16; off; off >>= 1) mx = fmaxf(mx, __shfl_xor_sync(0xffffffffu, mx, off));
    if ((tid & 31) == 0) red[tid >> 5] = mx;
    __syncthreads();
    mx = red[0];
#pragma unroll
    for (int j = 1; j < 8; j++) mx = fmaxf(mx, red[j]);
    __syncthreads();

    float e[8], sum = 0.f;
#pragma unroll
    for (int j = 0; j < 8; j++) {
        e[j] = ok[j] ? expf(v[j] - mx) : 0.f;
        sum += e[j];
    }
#pragma unroll
    for (int off = 16; off; off >>= 1) sum += __shfl_xor_sync(0xffffffffu, sum, off);
    if ((tid & 31) == 0) red[tid >> 5] = sum;
    __syncthreads();
    sum = 0.f;
#pragma unroll
    for (int j = 0; j < 8; j++) sum += red[j];
    float inv = 1.f / sum;
#pragma unroll
    for (int j = 0; j < 8; j++) {
        int t = tid + j * 256;
        __nv_bfloat16 hh, ll; bsplit(e[j] * inv, hh, ll);
        ph[t] = hh; pl[t] = ll;
    }
}

// ======================= 3-term HMMA GEMM (attention) =======================
// C[m,n] = alpha * sum_k (Ah+Al)[m,k] * (Bh+Bl)[n,k]   (lo*lo dropped)
#define STAGE_BYTES 32768
#define GEMM_SMEM   65536

template<bool CAUSAL, bool KCLIP>
__global__ void __launch_bounds__(256, 1)
gemm_mma(const __nv_bfloat16* __restrict__ Ah, const __nv_bfloat16* __restrict__ Al,
         const __nv_bfloat16* __restrict__ Bh, const __nv_bfloat16* __restrict__ Bl,
         float* __restrict__ C,
         int lda, int ldb, int ldc, int K, float alpha,
         long long aStr, long long bStr, long long cStr)
{
    int m0 = blockIdx.y * 128, n0 = blockIdx.x * 128;
    if (CAUSAL && n0 > m0) return;
    size_t z = blockIdx.z;
    Ah += z * aStr; Al += z * aStr;
    Bh += z * bStr; Bl += z * bStr;
    C  += z * cStr;
    int kEnd = KCLIP ? min(K, m0 + 128) : K;
    int S = kEnd >> 5;

    extern __shared__ char smem[];
    uint32_t sb = smem_u32(smem);
    int tid = threadIdx.x, lane = tid & 31, wid = tid >> 5;
    int wm = wid >> 2, wn = wid & 3;

    const __nv_bfloat16* Ahm = Ah + (size_t)m0 * lda;
    const __nv_bfloat16* Alm = Al + (size_t)m0 * lda;
    const __nv_bfloat16* Bhn = Bh + (size_t)n0 * ldb;
    const __nv_bfloat16* Bln = Bl + (size_t)n0 * ldb;

    float acc[4][4][4];
#pragma unroll
    for (int i = 0; i < 4; i++)
#pragma unroll
        for (int j = 0; j < 4; j++)
#pragma unroll
            for (int r = 0; r < 4; r++) acc[i][j][r] = 0.f;

    auto prefetch = [&](int s) {
        int k0 = s * 32;
        uint32_t buf = sb + (uint32_t)(s & 1) * STAGE_BYTES;
#pragma unroll
        for (int j = 0; j < 4; j++) {
            int id = tid + j * 256;
            int row = id >> 3, ch = id & 7;
            const __nv_bfloat16* src =
                (ch < 4 ? Ahm : Alm) + (size_t)row * lda + k0 + (ch & 3) * 8;
            CPASYNC16(buf + SW128((uint32_t)(row * 128 + ch * 16)), src);
        }
#pragma unroll
        for (int j = 0; j < 4; j++) {
            int id = tid + j * 256;
            int row = id >> 3, ch = id & 7;
            const __nv_bfloat16* src =
                (ch < 4 ? Bhn : Bln) + (size_t)row * ldb + k0 + (ch & 3) * 8;
            CPASYNC16(buf + 16384u + SW128((uint32_t)(row * 128 + ch * 16)), src);
        }
    };

    auto compute = [&](int s) {
        uint32_t bufA = sb + (uint32_t)(s & 1) * STAGE_BYTES;
        uint32_t bufB = bufA + 16384u;
        int la = lane & 15;
#pragma unroll
        for (int kk = 0; kk < 2; kk++) {
            uint32_t ah[4][4], al[4][4], bh[4][2], bl[4][2];
#pragma unroll
            for (int i = 0; i < 4; i++) {
                uint32_t row = (uint32_t)(wm * 64 + i * 16 + (lane & 15));
                uint32_t colh = (uint32_t)(kk * 32 + (lane >> 4) * 16);
                LDSM4(ah[i][0], ah[i][1], ah[i][2], ah[i][3],
                      bufA + SW128(row * 128 + colh));
                LDSM4(al[i][0], al[i][1], al[i][2], al[i][3],
                      bufA + SW128(row * 128 + 64 + colh));
            }
#pragma unroll
            for (int j = 0; j < 4; j++) {
                uint32_t row = (uint32_t)(wn * 32 + j * 8 + (la & 7));
                uint32_t colh = (uint32_t)(kk * 32 + (la >> 3) * 16);
                LDSM2(bh[j][0], bh[j][1], bufB + SW128(row * 128 + colh));
                LDSM2(bl[j][0], bl[j][1], bufB + SW128(row * 128 + 64 + colh));
            }
#pragma unroll
            for (int i = 0; i < 4; i++)
#pragma unroll
                for (int j = 0; j < 4; j++) {
                    MMA16816(acc[i][j], ah[i], bh[j]);
                    MMA16816(acc[i][j], ah[i], bl[j]);
                    MMA16816(acc[i][j], al[i], bh[j]);
                }
        }
    };

    prefetch(0); CPCOMMIT();
    for (int s = 0; s < S; s++) {
        if (s + 1 < S) { prefetch(s + 1); CPCOMMIT(); CPWAIT1(); }
        else           { CPWAIT0(); }
        __syncthreads();
        compute(s);
        __syncthreads();
    }

    int r0 = m0 + wm * 64, c0 = n0 + wn * 32;
#pragma unroll
    for (int i = 0; i < 4; i++)
#pragma unroll
        for (int j = 0; j < 4; j++) {
            int row = r0 + i * 16 + (lane >> 2);
            int col = c0 + j * 8 + (lane & 3) * 2;
            float2 o0 = make_float2(acc[i][j][0] * alpha, acc[i][j][1] * alpha);
            float2 o1 = make_float2(acc[i][j][2] * alpha, acc[i][j][3] * alpha);
            *reinterpret_cast<float2*>(C + (size_t)row * ldc + col) = o0;
            *reinterpret_cast<float2*>(C + (size_t)(row + 8) * ldc + col) = o1;
        }
}

// ======================= 2-term exact-ternary GEMM (weights) =======================
// C[m,n] = sum_g scale[n,g] * sum_{k in g} (Ah+Al)[m,k] * q[n,k]
// q exact bf16 ternary; per-128-K-group rescale of a separate accumulator.
// SMEM stage: A 128 rows x 128B [xh|xl] SW128, B 128 rows x 64B [q] SW64. 24KB/stage.
#define T_STAGE      24576
#define GEMM_SMEM_T  49152

__global__ void __launch_bounds__(256, 1)
gemm_tern(const __nv_bfloat16* __restrict__ Ah, const __nv_bfloat16* __restrict__ Al,
          const __nv_bfloat16* __restrict__ Q, const float* __restrict__ Sc,
          float* __restrict__ C,
          int lda, int ldb, int ldc, int K,
          long long aStr, long long bStr, long long cStr, long long sStr)
{
    int m0 = blockIdx.y * 128, n0 = blockIdx.x * 128;
    size_t z = blockIdx.z;
    Ah += z * aStr; Al += z * aStr;
    Q  += z * bStr; Sc += z * sStr;
    C  += z * cStr;
    int S = K >> 5, G = K >> 7;

    extern __shared__ char smem[];
    uint32_t sb = smem_u32(smem);
    int tid = threadIdx.x, lane = tid & 31, wid = tid >> 5;
    int wm = wid >> 2, wn = wid & 3;

    const __nv_bfloat16* Ahm = Ah + (size_t)m0 * lda;
    const __nv_bfloat16* Alm = Al + (size_t)m0 * lda;
    const __nv_bfloat16* Qn  = Q  + (size_t)n0 * ldb;

    float acc[4][4][4];
#pragma unroll
    for (int i = 0; i < 4; i++)
#pragma unroll
        for (int j = 0; j < 4; j++)
#pragma unroll
            for (int r = 0; r < 4; r++) acc[i][j][r] = 0.f;

    auto prefetch = [&](int s) {
        int k0 = s * 32;
        uint32_t buf = sb + (uint32_t)(s & 1) * T_STAGE;
#pragma unroll
        for (int j = 0; j < 4; j++) {          // A: 1024 chunks
            int id = tid + j * 256;
            int row = id >> 3, ch = id & 7;
            const __nv_bfloat16* src =
                (ch < 4 ? Ahm : Alm) + (size_t)row * lda + k0 + (ch & 3) * 8;
            CPASYNC16(buf + SW128((uint32_t)(row * 128 + ch * 16)), src);
        }
#pragma unroll
        for (int j = 0; j < 2; j++) {          // B (q): 512 chunks, 64B rows
            int id = tid + j * 256;
            int row = id >> 2, c = id & 3;
            const __nv_bfloat16* src = Qn + (size_t)row * ldb + k0 + c * 8;
            CPASYNC16(buf + 16384u + SW64((uint32_t)(row * 64 + c * 16)), src);
        }
    };

    float accg[4][4][4];

    auto compute = [&](int s) {
        uint32_t bufA = sb + (uint32_t)(s & 1) * T_STAGE;
        uint32_t bufB = bufA + 16384u;
        int la = lane & 15;
#pragma unroll
        for (int kk = 0; kk < 2; kk++) {
            uint32_t ah[4][4], al[4][4], bq[4][2];
#pragma unroll
            for (int i = 0; i < 4; i++) {
                uint32_t row = (uint32_t)(wm * 64 + i * 16 + (lane & 15));
                uint32_t colh = (uint32_t)(kk * 32 + (lane >> 4) * 16);
                LDSM4(ah[i][0], ah[i][1], ah[i][2], ah[i][3],
                      bufA + SW128(row * 128 + colh));
                LDSM4(al[i][0], al[i][1], al[i][2], al[i][3],
                      bufA + SW128(row * 128 + 64 + colh));
            }
#pragma unroll
            for (int j = 0; j < 4; j++) {
                uint32_t row = (uint32_t)(wn * 32 + j * 8 + (la & 7));
                uint32_t col = (uint32_t)(kk * 32 + (la >> 3) * 16);
                LDSM2(bq[j][0], bq[j][1], bufB + SW64(row * 64 + col));
            }
#pragma unroll
            for (int i = 0; i < 4; i++)
#pragma unroll
                for (int j = 0; j < 4; j++) {
                    MMA16816(accg[i][j], ah[i], bq[j]);
                    MMA16816(accg[i][j], al[i], bq[j]);
                }
        }
    };

    prefetch(0); CPCOMMIT();
    for (int g = 0; g < G; g++) {
#pragma unroll
        for (int i = 0; i < 4; i++)
#pragma unroll
            for (int j = 0; j < 4; j++)
#pragma unroll
                for (int r = 0; r < 4; r++) accg[i][j][r] = 0.f;

#pragma unroll
        for (int s4 = 0; s4 < 4; s4++) {
            int s = g * 4 + s4;
            if (s + 1 < S) { prefetch(s + 1); CPCOMMIT(); CPWAIT1(); }
            else           { CPWAIT0(); }
            __syncthreads();
            compute(s);
            __syncthreads();
        }
        // rescale: acc += scale[n,g] * accg
#pragma unroll
        for (int j = 0; j < 4; j++) {
            int col = n0 + wn * 32 + j * 8 + (lane & 3) * 2;
            float s0 = __ldg(Sc + (size_t)col * G + g);
            float s1 = __ldg(Sc + (size_t)(col + 1) * G + g);
#pragma unroll
            for (int i = 0; i < 4; i++) {
                acc[i][j][0] = fmaf(s0, accg[i][j][0], acc[i][j][0]);
                acc[i][j][1] = fmaf(s1, accg[i][j][1], acc[i][j][1]);
                acc[i][j][2] = fmaf(s0, accg[i][j][2], acc[i][j][2]);
                acc[i][j][3] = fmaf(s1, accg[i][j][3], acc[i][j][3]);
            }
        }
    }

    int r0 = m0 + wm * 64, c0 = n0 + wn * 32;
#pragma unroll
    for (int i = 0; i < 4; i++)
#pragma unroll
        for (int j = 0; j < 4; j++) {
            int row = r0 + i * 16 + (lane >> 2);
            int col = c0 + j * 8 + (lane & 3) * 2;
            float2 o0 = make_float2(acc[i][j][0], acc[i][j][1]);
            float2 o1 = make_float2(acc[i][j][2], acc[i][j][3]);
            *reinterpret_cast<float2*>(C + (size_t)row * ldc + col) = o0;
            *reinterpret_cast<float2*>(C + (size_t)(row + 8) * ldc + col) = o1;
        }
}

// ======================= launch =======================
extern "C" void kernel_launch(void* const* d_in, const int* in_sizes, int n_in,
                              void* d_out, int out_size) {
    const float* x    = (const float*)d_in[0];
    const int*   mask = (const int*)d_in[1];
    const float* w_in[4] = {(const float*)d_in[2], (const float*)d_in[3],
                            (const float*)d_in[4], (const float*)d_in[5]};
    float* out = (float*)d_out;

    __nv_bfloat16 *p_wq, *p_xh, *p_xl, *p_qh, *p_ql, *p_kh, *p_kl;
    __nv_bfloat16 *p_vth, *p_vtl, *p_ph, *p_pl, *p_ah, *p_al;
    float *p_wsc, *p_proj, *p_scores, *p_attn;
    cudaGetSymbolAddress((void**)&p_wq,     g_wq);
    cudaGetSymbolAddress((void**)&p_wsc,    g_wsc);
    cudaGetSymbolAddress((void**)&p_xh,     g_xh);
    cudaGetSymbolAddress((void**)&p_xl,     g_xl);
    cudaGetSymbolAddress((void**)&p_proj,   g_proj);
    cudaGetSymbolAddress((void**)&p_qh,     g_qh);
    cudaGetSymbolAddress((void**)&p_ql,     g_ql);
    cudaGetSymbolAddress((void**)&p_kh,     g_kh);
    cudaGetSymbolAddress((void**)&p_kl,     g_kl);
    cudaGetSymbolAddress((void**)&p_vth,    g_vth);
    cudaGetSymbolAddress((void**)&p_vtl,    g_vtl);
    cudaGetSymbolAddress((void**)&p_scores, g_scores);
    cudaGetSymbolAddress((void**)&p_ph,     g_ph);
    cudaGetSymbolAddress((void**)&p_pl,     g_pl);
    cudaGetSymbolAddress((void**)&p_attn,   g_attn);
    cudaGetSymbolAddress((void**)&p_ah,     g_ah);
    cudaGetSymbolAddress((void**)&p_al,     g_al);

    cudaFuncSetAttribute(gemm_mma<true, false>,
        cudaFuncAttributeMaxDynamicSharedMemorySize, GEMM_SMEM);
    cudaFuncSetAttribute(gemm_mma<false, true>,
        cudaFuncAttributeMaxDynamicSharedMemorySize, GEMM_SMEM);
    cudaFuncSetAttribute(gemm_tern,
        cudaFuncAttributeMaxDynamicSharedMemorySize, GEMM_SMEM_T);

    rope_tables_kernel<<<SQ, HALF>>>();

    for (int m = 0; m < 4; m++)
        quantize_tern_kernel<<<(HID * HID / GS) / 8, 256>>>(
            w_in[m], p_wq + (size_t)m * HID * HID, p_wsc + (size_t)m * HID * 16);

    split_kernel<<<(SQ * HID) / 1024, 256>>>(x, p_xh, p_xl);

    // q,k,v projections batched over z (exact-ternary 2-term path)
    gemm_tern<<<dim3(16, 16, 3), 256, GEMM_SMEM_T>>>(
        p_xh, p_xl, p_wq, p_wsc, p_proj,
        HID, HID, HID, HID,
        0LL, (long long)HID * HID, (long long)SQ * HID, (long long)HID * 16);

    rope_reshape_kernel<<<dim3(SQ, NH), HALF>>>(0);
    rope_reshape_kernel<<<dim3(SQ, NH), HALF>>>(1);
    vt_split_kernel<<<dim3(SQ / 32, HD / 32, NH), dim3(32, 8)>>>();

    // scores = (Q K^T)/sqrt(128), causal tile skip, batched over heads
    gemm_mma<true, false><<<dim3(16, 16, NH), 256, GEMM_SMEM>>>(
        p_qh, p_ql, p_kh, p_kl, p_scores,
        HD, HD, SQ, HD, 0.08838834764831845f,
        (long long)SQ * HD, (long long)SQ * HD, (long long)SQ * SQ);

    softmax_kernel<<<dim3(SQ, NH), 256>>>(mask);

    // attn = P @ V (B = V transposed to K-major), causal K-clip
    gemm_mma<false, true><<<dim3(1, 16, NH), 256, GEMM_SMEM>>>(
        p_ph, p_pl, p_vth, p_vtl, p_attn,
        SQ, SQ, HID, SQ, 1.0f,
        (long long)SQ * SQ, (long long)HD * SQ, (long long)HD);

    split_kernel<<<(SQ * HID) / 1024, 256>>>(p_attn, p_ah, p_al);

    // output projection (exact-ternary 2-term path)
    gemm_tern<<<dim3(16, 16, 1), 256, GEMM_SMEM_T>>>(
        p_ah, p_al, p_wq + 3 * (size_t)HID * HID, p_wsc + 3 * (size_t)HID * 16, out,
        HID, HID, HID, HID, 0LL, 0LL, 0LL, 0LL);
}

// round 10
// speedup vs baseline: 3.8006x; 1.3452x over previous
#include <cuda_runtime.h>
#include <cuda_bf16.h>
#include <cuda_fp16.h>
#include <math.h>
#include <stdint.h>

#define SQ   2048
#define HID  2048
#define NH   16
#define HD   128
#define HALF 64
#define GS   128
#define NEG_INF (-3.402823e38f)

// ======================= PTX helpers (baseline sm_103 — NO tcgen05) =======================
__device__ __forceinline__ uint32_t smem_u32(const void* p) {
    uint32_t a;
    asm("{ .reg .u64 t; cvta.to.shared.u64 t, %1; cvt.u32.u64 %0, t; }" : "=r"(a) : "l"(p));
    return a;
}
#define SW128(o) ((o) ^ (((o) >> 3) & 0x70))
#define SW64(o)  ((o) ^ (((o) >> 3) & 0x30))

#define CPASYNC16(dst, src) \
    asm volatile("cp.async.cg.shared.global [%0], [%1], 16;" :: "r"(dst), "l"(src))
#define CPCOMMIT() asm volatile("cp.async.commit_group;" ::: "memory")
#define CPWAIT1()  asm volatile("cp.async.wait_group 1;" ::: "memory")

#define LDSM4(r, addr) \
    asm volatile("ldmatrix.sync.aligned.m8n8.x4.shared.b16 {%0,%1,%2,%3}, [%4];" \
                 : "=r"((r)[0]), "=r"((r)[1]), "=r"((r)[2]), "=r"((r)[3]) : "r"(addr))
#define LDSM2(r, addr) \
    asm volatile("ldmatrix.sync.aligned.m8n8.x2.shared.b16 {%0,%1}, [%2];" \
                 : "=r"((r)[0]), "=r"((r)[1]) : "r"(addr))

#define MMA_BF16(d, a, b) \
    asm volatile("mma.sync.aligned.m16n8k16.row.col.f32.bf16.bf16.f32 " \
                 "{%0,%1,%2,%3}, {%4,%5,%6,%7}, {%8,%9}, {%0,%1,%2,%3};" \
                 : "+f"((d)[0]), "+f"((d)[1]), "+f"((d)[2]), "+f"((d)[3]) \
                 : "r"((a)[0]), "r"((a)[1]), "r"((a)[2]), "r"((a)[3]), \
                   "r"((b)[0]), "r"((b)[1]))
#define MMA_F16(d, a, b) \
    asm volatile("mma.sync.aligned.m16n8k16.row.col.f32.f16.f16.f32 " \
                 "{%0,%1,%2,%3}, {%4,%5,%6,%7}, {%8,%9}, {%0,%1,%2,%3};" \
                 : "+f"((d)[0]), "+f"((d)[1]), "+f"((d)[2]), "+f"((d)[3]) \
                 : "r"((a)[0]), "r"((a)[1]), "r"((a)[2]), "r"((a)[3]), \
                   "r"((b)[0]), "r"((b)[1]))

// ======================= device scratch =======================
__device__ __nv_bfloat16 g_wq[4][(size_t)HID * HID];
__device__ float         g_wsc[4][(size_t)HID * 16];
__device__ __nv_bfloat16 g_xh[(size_t)SQ * HID];
__device__ __nv_bfloat16 g_xl[(size_t)SQ * HID];
__device__ float         g_proj[3][(size_t)SQ * HID];
__device__ __nv_bfloat16 g_qh[NH][SQ * HD], g_ql[NH][SQ * HD];
__device__ __nv_bfloat16 g_kh[NH][SQ * HD], g_kl[NH][SQ * HD];
__device__ __half        g_vth[NH][HD * SQ], g_vtl[NH][HD * SQ];  // V^T [d][s] fp16 hi/lo
__device__ float         g_attn[(size_t)SQ * HID];
__device__ __nv_bfloat16 g_ah[(size_t)SQ * HID], g_al[(size_t)SQ * HID];
__device__ float         g_cos[SQ * HALF], g_sin[SQ * HALF];

__device__ __forceinline__ void bsplit(float x, __nv_bfloat16& h, __nv_bfloat16& l) {
    h = __float2bfloat16(x);
    l = __float2bfloat16(x - __bfloat162float(h));
}

// ======================= small kernels =======================
__global__ void rope_tables_kernel() {
    int s = blockIdx.x, i = threadIdx.x;
    float inv = (float)(1.0 / pow(10000.0, (double)i / 64.0));
    float ph = (float)s * inv;
    g_cos[s * HALF + i] = cosf(ph);
    g_sin[s * HALF + i] = sinf(ph);
}

__global__ void quantize_tern_kernel(const float* __restrict__ w,
                                     __nv_bfloat16* __restrict__ q,
                                     float* __restrict__ sc) {
    int gid  = blockIdx.x * 8 + (threadIdx.x >> 5);
    int lane = threadIdx.x & 31;
    size_t base = (size_t)gid * GS + lane * 4;
    float4 v = *reinterpret_cast<const float4*>(w + base);
    float s = fabsf(v.x) + fabsf(v.y) + fabsf(v.z) + fabsf(v.w);
#pragma unroll
    for (int off = 16; off; off >>= 1) s += __shfl_xor_sync(0xffffffffu, s, off);
    float scale = fmaxf(s * 0.0078125f, 1e-8f);
    float vv[4] = {v.x, v.y, v.z, v.w};
    __nv_bfloat16 qv[4];
#pragma unroll
    for (int j = 0; j < 4; j++) {
        float wn = vv[j] / scale;
        qv[j] = __float2bfloat16((wn > 0.5f) ? 1.0f : ((wn < -0.5f) ? -1.0f : 0.0f));
    }
    reinterpret_cast<__nv_bfloat162*>(q + base)[0] = {qv[0], qv[1]};
    reinterpret_cast<__nv_bfloat162*>(q + base)[1] = {qv[2], qv[3]};
    if (lane == 0) sc[gid] = scale;
}

__global__ void split_kernel(const float* __restrict__ x,
                             __nv_bfloat16* __restrict__ oh,
                             __nv_bfloat16* __restrict__ ol) {
    size_t i = ((size_t)blockIdx.x * 256 + threadIdx.x) * 4;
    float4 v = *reinterpret_cast<const float4*>(x + i);
    float vv[4] = {v.x, v.y, v.z, v.w};
    __nv_bfloat16 h[4], l[4];
#pragma unroll
    for (int j = 0; j < 4; j++) bsplit(vv[j], h[j], l[j]);
    reinterpret_cast<__nv_bfloat162*>(oh + i)[0] = {h[0], h[1]};
    reinterpret_cast<__nv_bfloat162*>(oh + i)[1] = {h[2], h[3]};
    reinterpret_cast<__nv_bfloat162*>(ol + i)[0] = {l[0], l[1]};
    reinterpret_cast<__nv_bfloat162*>(ol + i)[1] = {l[2], l[3]};
}

__global__ void rope_reshape_kernel(int which) {
    int s = blockIdx.x, h = blockIdx.y, d = threadIdx.x;  // d in [0,64)
    const float* src = g_proj[which] + (size_t)s * HID + h * HD;
    float x1 = src[d], x2 = src[d + HALF];
    float c = g_cos[s * HALF + d], sn = g_sin[s * HALF + d];
    float o1 = x1 * c - x2 * sn;
    float o2 = x1 * sn + x2 * c;
    __nv_bfloat16 h1, l1, h2, l2;
    bsplit(o1, h1, l1); bsplit(o2, h2, l2);
    __nv_bfloat16* dh = (which == 0 ? g_qh[h] : g_kh[h]) + (size_t)s * HD;
    __nv_bfloat16* dl = (which == 0 ? g_ql[h] : g_kl[h]) + (size_t)s * HD;
    dh[d] = h1; dh[d + HALF] = h2;
    dl[d] = l1; dl[d + HALF] = l2;
}

// transpose V projection -> per-head [d][s] fp16 hi/lo
__global__ void vt_split_kernel() {
    __shared__ float t[32][33];
    int h = blockIdx.z, s0 = blockIdx.x * 32, d0 = blockIdx.y * 32;
    const float* src = g_proj[2] + (size_t)h * HD;
    for (int i = threadIdx.y; i < 32; i += 8)
        t[i][threadIdx.x] = src[(size_t)(s0 + i) * HID + d0 + threadIdx.x];
    __syncthreads();
    for (int i = threadIdx.y; i < 32; i += 8) {
        float v = t[threadIdx.x][i];
        __half hh = __float2half(v);
        __half ll = __float2half(v - __half2float(hh));
        size_t off = (size_t)(d0 + i) * SQ + s0 + threadIdx.x;
        g_vth[h][off] = hh; g_vtl[h][off] = ll;
    }
}

// ======================= flash attention =======================
// CTA: 128 Q rows x 1 head. QK^T bf16 3-term, online softmax, P fp16, PV fp16 2-term.
// SMEM: Q 64K | bufA(K) 64K | bufB(V) 64K | P 32K | red 2K  = 231424 B
#define FL_SMEM 231424
#define FL_SCALE 0.08838834764831845f

__global__ void __launch_bounds__(256, 1)
flash_kernel(const int* __restrict__ mask, float* __restrict__ attn) {
    int h  = blockIdx.x;
    int qb = 15 - (int)blockIdx.y;          // heavy blocks first
    extern __shared__ char smem[];
    uint32_t sb = smem_u32(smem);
    const uint32_t Qb = sb, Ab = sb + 65536u, Bb = sb + 131072u, Pb = sb + 196608u;
    float* red = reinterpret_cast<float*>(smem + 229376);
    int tid = threadIdx.x, lane = tid & 31, wid = tid >> 5;
    int wm = wid >> 2, wn = wid & 3, la = lane & 15;

    const __nv_bfloat16* qhp = g_qh[h]; const __nv_bfloat16* qlp = g_ql[h];
    const __nv_bfloat16* khp = g_kh[h]; const __nv_bfloat16* klp = g_kl[h];
    const __half* vhp = g_vth[h]; const __half* vlp = g_vtl[h];

    // Q tile (once)
#pragma unroll
    for (int j = 0; j < 16; j++) {
        int c = tid + j * 256; int b = c >> 10, id = c & 1023, row = id >> 3, ch = id & 7;
        const __nv_bfloat16* src = (ch < 4 ? qhp : qlp)
            + (size_t)(qb * 128 + row) * HD + b * 32 + (ch & 3) * 8;
        CPASYNC16(Qb + b * 16384u + SW128((uint32_t)(row * 128 + ch * 16)), src);
    }
    CPCOMMIT();

    auto load_k = [&](int kb) {
#pragma unroll
        for (int j = 0; j < 16; j++) {
            int c = tid + j * 256; int b = c >> 10, id = c & 1023, row = id >> 3, ch = id & 7;
            const __nv_bfloat16* src = (ch < 4 ? khp : klp)
                + (size_t)(kb * 128 + row) * HD + b * 32 + (ch & 3) * 8;
            CPASYNC16(Ab + b * 16384u + SW128((uint32_t)(row * 128 + ch * 16)), src);
        }
    };
    auto load_v = [&](int kb) {
#pragma unroll
        for (int j = 0; j < 16; j++) {
            int c = tid + j * 256; int b = c >> 10, id = c & 1023, row = id >> 3, ch = id & 7;
            const __half* src = (ch < 4 ? vhp : vlp)
                + (size_t)row * SQ + kb * 128 + b * 32 + (ch & 3) * 8;
            CPASYNC16(Bb + b * 16384u + SW128((uint32_t)(row * 128 + ch * 16)), src);
        }
    };
    load_k(0); CPCOMMIT();
    load_v(0); CPCOMMIT();

    float o[4][4][4];
    float mrow[4][2], lrow[4][2];
#pragma unroll
    for (int i = 0; i < 4; i++) {
#pragma unroll
        for (int j = 0; j < 4; j++)
#pragma unroll
            for (int r = 0; r < 4; r++) o[i][j][r] = 0.f;
        mrow[i][0] = NEG_INF; mrow[i][1] = NEG_INF;
        lrow[i][0] = 0.f;     lrow[i][1] = 0.f;
    }

    for (int s = 0; s <= qb; s++) {
        CPWAIT1();            // K_s (+Q) landed; newest (V_s) may be in flight
        __syncthreads();      // #1 visibility

        // ---- S = Qh*Kh + Qh*Kl + Ql*Kh ----
        float sacc[4][4][4];
#pragma unroll
        for (int i = 0; i < 4; i++)
#pragma unroll
            for (int j = 0; j < 4; j++)
#pragma unroll
                for (int r = 0; r < 4; r++) sacc[i][j][r] = 0.f;
#pragma unroll
        for (int kk = 0; kk < 8; kk++) {
            int b = kk >> 1, klo = kk & 1;
            uint32_t qh4[4][4], ql4[4][4], kh2[4][2], kl2[4][2];
#pragma unroll
            for (int i = 0; i < 4; i++) {
                uint32_t row = (uint32_t)(wm * 64 + i * 16 + la);
                uint32_t colh = (uint32_t)(klo * 32 + (lane >> 4) * 16);
                LDSM4(qh4[i], Qb + b * 16384u + SW128(row * 128 + colh));
                LDSM4(ql4[i], Qb + b * 16384u + SW128(row * 128 + 64 + colh));
            }
#pragma unroll
            for (int j = 0; j < 4; j++) {
                uint32_t krow = (uint32_t)(wn * 32 + j * 8 + (la & 7));
                uint32_t kc = (uint32_t)(klo * 32 + (la >> 3) * 16);
                LDSM2(kh2[j], Ab + b * 16384u + SW128(krow * 128 + kc));
                LDSM2(kl2[j], Ab + b * 16384u + SW128(krow * 128 + 64 + kc));
            }
#pragma unroll
            for (int i = 0; i < 4; i++)
#pragma unroll
                for (int j = 0; j < 4; j++) {
                    MMA_BF16(sacc[i][j], qh4[i], kh2[j]);
                    MMA_BF16(sacc[i][j], qh4[i], kl2[j]);
                    MMA_BF16(sacc[i][j], ql4[i], kh2[j]);
                }
        }

        // ---- scale + mask ----
        bool diag = (s == qb);
#pragma unroll
        for (int j = 0; j < 4; j++) {
            int c0 = wn * 32 + j * 8 + (lane & 3) * 2;
            int cg = s * 128 + c0;
            bool mk0 = (__ldg(mask + cg) != 0), mk1 = (__ldg(mask + cg + 1) != 0);
#pragma unroll
            for (int i = 0; i < 4; i++) {
                int rg0 = qb * 128 + wm * 64 + i * 16 + (lane >> 2);
                int rg1 = rg0 + 8;
                float v0 = sacc[i][j][0] * FL_SCALE;
                float v1 = sacc[i][j][1] * FL_SCALE;
                float v2 = sacc[i][j][2] * FL_SCALE;
                float v3 = sacc[i][j][3] * FL_SCALE;
                if (!mk0 || (diag && cg     > rg0)) v0 = NEG_INF;
                if (!mk1 || (diag && cg + 1 > rg0)) v1 = NEG_INF;
                if (!mk0 || (diag && cg     > rg1)) v2 = NEG_INF;
                if (!mk1 || (diag && cg + 1 > rg1)) v3 = NEG_INF;
                sacc[i][j][0] = v0; sacc[i][j][1] = v1;
                sacc[i][j][2] = v2; sacc[i][j][3] = v3;
            }
        }

        // ---- row max (cross-warp via red) ----
        float mx[4][2];
#pragma unroll
        for (int i = 0; i < 4; i++) {
            float a0 = NEG_INF, a1 = NEG_INF;
#pragma unroll
            for (int j = 0; j < 4; j++) {
                a0 = fmaxf(a0, fmaxf(sacc[i][j][0], sacc[i][j][1]));
                a1 = fmaxf(a1, fmaxf(sacc[i][j][2], sacc[i][j][3]));
            }
            a0 = fmaxf(a0, __shfl_xor_sync(0xffffffffu, a0, 1));
            a0 = fmaxf(a0, __shfl_xor_sync(0xffffffffu, a0, 2));
            a1 = fmaxf(a1, __shfl_xor_sync(0xffffffffu, a1, 1));
            a1 = fmaxf(a1, __shfl_xor_sync(0xffffffffu, a1, 2));
            mx[i][0] = a0; mx[i][1] = a1;
            if ((lane & 3) == 0) {
                int r0 = wm * 64 + i * 16 + (lane >> 2);
                red[r0 * 4 + wn] = a0;
                red[(r0 + 8) * 4 + wn] = a1;
            }
        }
        __syncthreads();  // #2

        float fsc[4][2], mnew[4][2];
#pragma unroll
        for (int i = 0; i < 4; i++)
#pragma unroll
            for (int rs = 0; rs < 2; rs++) {
                int r0 = wm * 64 + i * 16 + (lane >> 2) + rs * 8;
                float4 rv = *reinterpret_cast<float4*>(red + r0 * 4);
                float rm = fmaxf(fmaxf(rv.x, rv.y), fmaxf(rv.z, rv.w));
                float mn = fmaxf(mrow[i][rs], rm);
                fsc[i][rs] = __expf(mrow[i][rs] - mn);
                mnew[i][rs] = mn;
                mrow[i][rs] = mn;
            }

        // ---- p = exp(s - m), partial row sums ----
        float ps[4][2];
#pragma unroll
        for (int i = 0; i < 4; i++) { ps[i][0] = 0.f; ps[i][1] = 0.f; }
#pragma unroll
        for (int i = 0; i < 4; i++)
#pragma unroll
            for (int j = 0; j < 4; j++) {
                float p0 = __expf(sacc[i][j][0] - mnew[i][0]);
                float p1 = __expf(sacc[i][j][1] - mnew[i][0]);
                float p2 = __expf(sacc[i][j][2] - mnew[i][1]);
                float p3 = __expf(sacc[i][j][3] - mnew[i][1]);
                sacc[i][j][0] = p0; sacc[i][j][1] = p1;
                sacc[i][j][2] = p2; sacc[i][j][3] = p3;
                ps[i][0] += p0 + p1; ps[i][1] += p2 + p3;
            }
        __syncthreads();  // #3 (red reads done before rewrite)
#pragma unroll
        for (int i = 0; i < 4; i++) {
            float a0 = ps[i][0], a1 = ps[i][1];
            a0 += __shfl_xor_sync(0xffffffffu, a0, 1);
            a0 += __shfl_xor_sync(0xffffffffu, a0, 2);
            a1 += __shfl_xor_sync(0xffffffffu, a1, 1);
            a1 += __shfl_xor_sync(0xffffffffu, a1, 2);
            if ((lane & 3) == 0) {
                int r0 = wm * 64 + i * 16 + (lane >> 2);
                red[r0 * 4 + wn] = a0;
                red[(r0 + 8) * 4 + wn] = a1;
            }
        }
        __syncthreads();  // #4
#pragma unroll
        for (int i = 0; i < 4; i++)
#pragma unroll
            for (int rs = 0; rs < 2; rs++) {
                int r0 = wm * 64 + i * 16 + (lane >> 2) + rs * 8;
                float4 rv = *reinterpret_cast<float4*>(red + r0 * 4);
                float rsum = rv.x + rv.y + rv.z + rv.w;
                lrow[i][rs] = lrow[i][rs] * fsc[i][rs] + rsum;
            }
        // rescale O
#pragma unroll
        for (int i = 0; i < 4; i++)
#pragma unroll
            for (int j = 0; j < 4; j++) {
                o[i][j][0] *= fsc[i][0]; o[i][j][1] *= fsc[i][0];
                o[i][j][2] *= fsc[i][1]; o[i][j][3] *= fsc[i][1];
            }

        // prefetch next K (bufA free: S-phase done for all warps at #2)
        if (s < qb) { load_k(s + 1); CPCOMMIT(); }

        // ---- store P (fp16) ----
#pragma unroll
        for (int i = 0; i < 4; i++)
#pragma unroll
            for (int j = 0; j < 4; j++) {
                int c0 = wn * 32 + j * 8 + (lane & 3) * 2;
                int b = c0 >> 5, cc = c0 & 31;
                int r0 = wm * 64 + i * 16 + (lane >> 2);
                __half2 h0 = __floats2half2_rn(sacc[i][j][0], sacc[i][j][1]);
                __half2 h1 = __floats2half2_rn(sacc[i][j][2], sacc[i][j][3]);
                uint32_t a0 = Pb + b * 8192u + SW64((uint32_t)(r0 * 64 + cc * 2));
                uint32_t a1 = Pb + b * 8192u + SW64((uint32_t)((r0 + 8) * 64 + cc * 2));
                asm volatile("st.shared.b32 [%0], %1;" :: "r"(a0), "r"(*(uint32_t*)&h0) : "memory");
                asm volatile("st.shared.b32 [%0], %1;" :: "r"(a1), "r"(*(uint32_t*)&h1) : "memory");
            }
        CPWAIT1();            // V_s landed (newest = K_{s+1})
        __syncthreads();      // #5 P + V visible

        // ---- O += P * (Vh + Vl) ----
#pragma unroll
        for (int kk = 0; kk < 8; kk++) {
            int b = kk >> 1, klo = kk & 1;
            uint32_t pf[4][4], vh2[4][2], vl2[4][2];
#pragma unroll
            for (int i = 0; i < 4; i++) {
                uint32_t row = (uint32_t)(wm * 64 + i * 16 + la);
                uint32_t pc = (uint32_t)(klo * 32 + (lane >> 4) * 16);
                LDSM4(pf[i], Pb + b * 8192u + SW64(row * 64 + pc));
            }
#pragma unroll
            for (int j = 0; j < 4; j++) {
                uint32_t vrow = (uint32_t)(wn * 32 + j * 8 + (la & 7));
                uint32_t vc = (uint32_t)(klo * 32 + (la >> 3) * 16);
                LDSM2(vh2[j], Bb + b * 16384u + SW128(vrow * 128 + vc));
                LDSM2(vl2[j], Bb + b * 16384u + SW128(vrow * 128 + 64 + vc));
            }
#pragma unroll
            for (int i = 0; i < 4; i++)
#pragma unroll
                for (int j = 0; j < 4; j++) {
                    MMA_F16(o[i][j], pf[i], vh2[j]);
                    MMA_F16(o[i][j], pf[i], vl2[j]);
                }
        }
        __syncthreads();      // #6 all done with V_s / P
        if (s < qb) { load_v(s + 1); CPCOMMIT(); }
    }

    // ---- epilogue: O / l -> g_attn[s][h*128+d] ----
#pragma unroll
    for (int i = 0; i < 4; i++) {
        float inv0 = 1.f / lrow[i][0], inv1 = 1.f / lrow[i][1];
        int r0 = qb * 128 + wm * 64 + i * 16 + (lane >> 2);
#pragma unroll
        for (int j = 0; j < 4; j++) {
            int col = h * 128 + wn * 32 + j * 8 + (lane & 3) * 2;
            float2 v0 = make_float2(o[i][j][0] * inv0, o[i][j][1] * inv0);
            float2 v1 = make_float2(o[i][j][2] * inv1, o[i][j][3] * inv1);
            *reinterpret_cast<float2*>(attn + (size_t)r0 * HID + col) = v0;
            *reinterpret_cast<float2*>(attn + (size_t)(r0 + 8) * HID + col) = v1;
        }
    }
}

// ======================= 2-term exact-ternary GEMM (weights), 3-stage =======================
#define T_STAGE      24576
#define GEMM_SMEM_T  73728

__global__ void __launch_bounds__(256, 1)
gemm_tern(const __nv_bfloat16* __restrict__ Ah, const __nv_bfloat16* __restrict__ Al,
          const __nv_bfloat16* __restrict__ Q, const float* __restrict__ Sc,
          float* __restrict__ C,
          int lda, int ldb, int ldc, int K,
          long long aStr, long long bStr, long long cStr, long long sStr)
{
    int m0 = blockIdx.y * 128, n0 = blockIdx.x * 128;
    size_t z = blockIdx.z;
    Ah += z * aStr; Al += z * aStr;
    Q  += z * bStr; Sc += z * sStr;
    C  += z * cStr;
    int S = K >> 5, G = K >> 7;

    extern __shared__ char smem[];
    uint32_t sb = smem_u32(smem);
    int tid = threadIdx.x, lane = tid & 31, wid = tid >> 5;
    int wm = wid >> 2, wn = wid & 3;

    const __nv_bfloat16* Ahm = Ah + (size_t)m0 * lda;
    const __nv_bfloat16* Alm = Al + (size_t)m0 * lda;
    const __nv_bfloat16* Qn  = Q  + (size_t)n0 * ldb;

    float acc[4][4][4];
#pragma unroll
    for (int i = 0; i < 4; i++)
#pragma unroll
        for (int j = 0; j < 4; j++)
#pragma unroll
            for (int r = 0; r < 4; r++) acc[i][j][r] = 0.f;

    auto prefetch = [&](int s) {
        int k0 = s * 32;
        uint32_t buf = sb + (uint32_t)(s % 3) * T_STAGE;
#pragma unroll
        for (int j = 0; j < 4; j++) {
            int id = tid + j * 256;
            int row = id >> 3, ch = id & 7;
            const __nv_bfloat16* src =
                (ch < 4 ? Ahm : Alm) + (size_t)row * lda + k0 + (ch & 3) * 8;
            CPASYNC16(buf + SW128((uint32_t)(row * 128 + ch * 16)), src);
        }
#pragma unroll
        for (int j = 0; j < 2; j++) {
            int id = tid + j * 256;
            int row = id >> 2, c = id & 3;
            const __nv_bfloat16* src = Qn + (size_t)row * ldb + k0 + c * 8;
            CPASYNC16(buf + 16384u + SW64((uint32_t)(row * 64 + c * 16)), src);
        }
    };

    float accg[4][4][4];

    auto compute = [&](int s) {
        uint32_t bufA = sb + (uint32_t)(s % 3) * T_STAGE;
        uint32_t bufB = bufA + 16384u;
        int la = lane & 15;
#pragma unroll
        for (int kk = 0; kk < 2; kk++) {
            uint32_t ah[4][4], al[4][4], bq[4][2];
#pragma unroll
            for (int i = 0; i < 4; i++) {
                uint32_t row = (uint32_t)(wm * 64 + i * 16 + (lane & 15));
                uint32_t colh = (uint32_t)(kk * 32 + (lane >> 4) * 16);
                LDSM4(ah[i], bufA + SW128(row * 128 + colh));
                LDSM4(al[i], bufA + SW128(row * 128 + 64 + colh));
            }
#pragma unroll
            for (int j = 0; j < 4; j++) {
                uint32_t row = (uint32_t)(wn * 32 + j * 8 + (la & 7));
                uint32_t col = (uint32_t)(kk * 32 + (la >> 3) * 16);
                LDSM2(bq[j], bufB + SW64(row * 64 + col));
            }
#pragma unroll
            for (int i = 0; i < 4; i++)
#pragma unroll
                for (int j = 0; j < 4; j++) {
                    MMA_BF16(accg[i][j], ah[i], bq[j]);
                    MMA_BF16(accg[i][j], al[i], bq[j]);
                }
        }
    };

    prefetch(0); CPCOMMIT();
    prefetch(1); CPCOMMIT();
    for (int g = 0; g < G; g++) {
#pragma unroll
        for (int i = 0; i < 4; i++)
#pragma unroll
            for (int j = 0; j < 4; j++)
#pragma unroll
                for (int r = 0; r < 4; r++) accg[i][j][r] = 0.f;

#pragma unroll
        for (int s4 = 0; s4 < 4; s4++) {
            int s = g * 4 + s4;
            CPWAIT1();
            __syncthreads();
            compute(s);
            if (s + 2 < S) { prefetch(s + 2); CPCOMMIT(); }
        }
#pragma unroll
        for (int j = 0; j < 4; j++) {
            int col = n0 + wn * 32 + j * 8 + (lane & 3) * 2;
            float s0 = __ldg(Sc + (size_t)col * G + g);
            float s1 = __ldg(Sc + (size_t)(col + 1) * G + g);
#pragma unroll
            for (int i = 0; i < 4; i++) {
                acc[i][j][0] = fmaf(s0, accg[i][j][0], acc[i][j][0]);
                acc[i][j][1] = fmaf(s1, accg[i][j][1], acc[i][j][1]);
                acc[i][j][2] = fmaf(s0, accg[i][j][2], acc[i][j][2]);
                acc[i][j][3] = fmaf(s1, accg[i][j][3], acc[i][j][3]);
            }
        }
    }

    int r0 = m0 + wm * 64, c0 = n0 + wn * 32;
#pragma unroll
    for (int i = 0; i < 4; i++)
#pragma unroll
        for (int j = 0; j < 4; j++) {
            int row = r0 + i * 16 + (lane >> 2);
            int col = c0 + j * 8 + (lane & 3) * 2;
            float2 o0 = make_float2(acc[i][j][0], acc[i][j][1]);
            float2 o1 = make_float2(acc[i][j][2], acc[i][j][3]);
            *reinterpret_cast<float2*>(C + (size_t)row * ldc + col) = o0;
            *reinterpret_cast<float2*>(C + (size_t)(row + 8) * ldc + col) = o1;
        }
}

// ======================= launch =======================
extern "C" void kernel_launch(void* const* d_in, const int* in_sizes, int n_in,
                              void* d_out, int out_size) {
    const float* x    = (const float*)d_in[0];
    const int*   mask = (const int*)d_in[1];
    const float* w_in[4] = {(const float*)d_in[2], (const float*)d_in[3],
                            (const float*)d_in[4], (const float*)d_in[5]};
    float* out = (float*)d_out;

    __nv_bfloat16 *p_wq, *p_xh, *p_xl, *p_ah, *p_al;
    float *p_wsc, *p_proj, *p_attn;
    cudaGetSymbolAddress((void**)&p_wq,   g_wq);
    cudaGetSymbolAddress((void**)&p_wsc,  g_wsc);
    cudaGetSymbolAddress((void**)&p_xh,   g_xh);
    cudaGetSymbolAddress((void**)&p_xl,   g_xl);
    cudaGetSymbolAddress((void**)&p_proj, g_proj);
    cudaGetSymbolAddress((void**)&p_attn, g_attn);
    cudaGetSymbolAddress((void**)&p_ah,   g_ah);
    cudaGetSymbolAddress((void**)&p_al,   g_al);

    cudaFuncSetAttribute(gemm_tern,
        cudaFuncAttributeMaxDynamicSharedMemorySize, GEMM_SMEM_T);
    cudaFuncSetAttribute(flash_kernel,
        cudaFuncAttributeMaxDynamicSharedMemorySize, FL_SMEM);

    rope_tables_kernel<<<SQ, HALF>>>();

    for (int m = 0; m < 4; m++)
        quantize_tern_kernel<<<(HID * HID / GS) / 8, 256>>>(
            w_in[m], p_wq + (size_t)m * HID * HID, p_wsc + (size_t)m * HID * 16);

    split_kernel<<<(SQ * HID) / 1024, 256>>>(x, p_xh, p_xl);

    // q,k,v projections batched over z (exact-ternary 2-term path)
    gemm_tern<<<dim3(16, 16, 3), 256, GEMM_SMEM_T>>>(
        p_xh, p_xl, p_wq, p_wsc, p_proj,
        HID, HID, HID, HID,
        0LL, (long long)HID * HID, (long long)SQ * HID, (long long)HID * 16);

    rope_reshape_kernel<<<dim3(SQ, NH), HALF>>>(0);
    rope_reshape_kernel<<<dim3(SQ, NH), HALF>>>(1);
    vt_split_kernel<<<dim3(SQ / 32, HD / 32, NH), dim3(32, 8)>>>();

    // fused attention: QK^T + causal softmax + PV
    flash_kernel<<<dim3(NH, 16), 256, FL_SMEM>>>(mask, p_attn);

    split_kernel<<<(SQ * HID) / 1024, 256>>>(p_attn, p_ah, p_al);

    // output projection (exact-ternary 2-term path)
    gemm_tern<<<dim3(16, 16, 1), 256, GEMM_SMEM_T>>>(
        p_ah, p_al, p_wq + 3 * (size_t)HID * HID, p_wsc + 3 * (size_t)HID * 16, out,
        HID, HID, HID, HID, 0LL, 0LL, 0LL, 0LL);
}